// round 1
// baseline (speedup 1.0000x reference)
#include <cuda_runtime.h>

#define B_ 8
#define C_ 64
#define H_ 256
#define W_ 256
#define HW_ (H_ * W_)

__global__ __launch_bounds__(256, 8)
void conv_attn_kernel(const float* __restrict__ q,
                      const float* __restrict__ k,
                      const float* __restrict__ v,
                      float* __restrict__ out)
{
    const int w = blockIdx.x * 32 + (threadIdx.x & 31);
    const int h = blockIdx.y * 8 + (threadIdx.x >> 5);
    const int b = blockIdx.z;

    const int base = (b * C_) * HW_ + h * W_ + w;

    // 3x3 neighborhood offsets + validity (zero-padded borders)
    int  off[9];
    bool val[9];
#pragma unroll
    for (int dy = 0; dy < 3; dy++) {
#pragma unroll
        for (int dx = 0; dx < 3; dx++) {
            const int i  = dy * 3 + dx;
            const int hh = h + dy - 1;
            const int ww = w + dx - 1;
            val[i] = (hh >= 0) && (hh < H_) && (ww >= 0) && (ww < W_);
            off[i] = (dy - 1) * W_ + (dx - 1);
        }
    }

    // Pass 1: scores s[i] = sum_c q[c] * k_shifted[i][c]
    float s[9];
#pragma unroll
    for (int i = 0; i < 9; i++) s[i] = 0.0f;

#pragma unroll 4
    for (int c = 0; c < C_; c++) {
        const int p = base + c * HW_;
        const float qv = __ldg(q + p);
#pragma unroll
        for (int i = 0; i < 9; i++) {
            if (val[i]) s[i] += qv * __ldg(k + p + off[i]);
        }
    }

    // Softmax over the 9 taps (OOB taps have score 0 — matches zero-pad ref)
    float m = s[0];
#pragma unroll
    for (int i = 1; i < 9; i++) m = fmaxf(m, s[i]);
    float sum = 0.0f;
#pragma unroll
    for (int i = 0; i < 9; i++) { s[i] = __expf(s[i] - m); sum += s[i]; }
    const float inv = 1.0f / sum;
#pragma unroll
    for (int i = 0; i < 9; i++) s[i] *= inv;

    // Pass 2: out[c] = sum_i w[i] * v_shifted[i][c]
#pragma unroll 2
    for (int c = 0; c < C_; c++) {
        const int p = base + c * HW_;
        float acc = 0.0f;
#pragma unroll
        for (int i = 0; i < 9; i++) {
            if (val[i]) acc = fmaf(s[i], __ldg(v + p + off[i]), acc);
        }
        out[p] = acc;
    }
}

extern "C" void kernel_launch(void* const* d_in, const int* in_sizes, int n_in,
                              void* d_out, int out_size)
{
    const float* q = (const float*)d_in[0];
    const float* k = (const float*)d_in[1];
    const float* v = (const float*)d_in[2];
    float* out = (float*)d_out;

    dim3 block(256);
    dim3 grid(W_ / 32, H_ / 8, B_);
    conv_attn_kernel<<<grid, block>>>(q, k, v, out);
}